// round 10
// baseline (speedup 1.0000x reference)
#include <cuda_runtime.h>
#include <cstdint>

#define CDIM 192
#define NHEADS 6
#define HDIM 32
#define NTOK 49
#define NWIN 4096
#define MROWS 200704
#define HID 768
#define QKSCALE 0.17677669529663687f

// ---------------- scratch buffers (static device memory; no allocs) --------
__device__ __align__(128) float g_win[(size_t)MROWS * CDIM];
__device__ __align__(128) float g_qkv[(size_t)MROWS * (3 * CDIM)];
__device__ __align__(128) float g_att[(size_t)MROWS * CDIM];
__device__ __align__(128) float g_x1[(size_t)MROWS * CDIM];
__device__ __align__(128) float g_y[(size_t)MROWS * CDIM];
__device__ __align__(128) float g_h1[(size_t)MROWS * HID];
__device__ __align__(128) float g_x0[(size_t)MROWS * CDIM];

__device__ __forceinline__ int map_row(int m, int shift) {
    int w = m / NTOK;
    int n = m - w * NTOK;
    int b = w >> 6;
    int widx = w & 63;
    int wy = widx >> 3, wx = widx & 7;
    int ty = n / 7, tx = n - ty * 7;
    int sy = wy * 7 + ty + shift; if (sy >= 56) sy -= 56;
    int sx = wx * 7 + tx + shift; if (sx >= 56) sx -= 56;
    return b * 3136 + sy * 56 + sx;
}

// ---------------- LayerNorm kernels ----------------------------------------
__global__ void ln_part_kernel(const float* __restrict__ x,
                               const float* __restrict__ gw,
                               const float* __restrict__ gb,
                               float* __restrict__ out, int shift)
{
    int t = blockIdx.x;
    int src = map_row(t, shift);
    int c = threadIdx.x;
    float v = x[(size_t)src * CDIM + c];
    __shared__ float sb[12];
    float s = v, s2 = v * v;
    #pragma unroll
    for (int o = 16; o; o >>= 1) {
        s  += __shfl_xor_sync(0xffffffffu, s, o);
        s2 += __shfl_xor_sync(0xffffffffu, s2, o);
    }
    int warp = c >> 5;
    if ((c & 31) == 0) { sb[warp] = s; sb[warp + 6] = s2; }
    __syncthreads();
    float ts = 0.f, ts2 = 0.f;
    #pragma unroll
    for (int i = 0; i < 6; i++) { ts += sb[i]; ts2 += sb[i + 6]; }
    float mu  = ts  * (1.0f / CDIM);
    float var = ts2 * (1.0f / CDIM) - mu * mu;
    float inv = rsqrtf(var + 1e-5f);
    out[(size_t)t * CDIM + c] = (v - mu) * inv * gw[c] + gb[c];
}

__global__ void ln_kernel(const float* __restrict__ x,
                          const float* __restrict__ gw,
                          const float* __restrict__ gb,
                          float* __restrict__ out)
{
    int t = blockIdx.x;
    int c = threadIdx.x;
    float v = x[(size_t)t * CDIM + c];
    __shared__ float sb[12];
    float s = v, s2 = v * v;
    #pragma unroll
    for (int o = 16; o; o >>= 1) {
        s  += __shfl_xor_sync(0xffffffffu, s, o);
        s2 += __shfl_xor_sync(0xffffffffu, s2, o);
    }
    int warp = c >> 5;
    if ((c & 31) == 0) { sb[warp] = s; sb[warp + 6] = s2; }
    __syncthreads();
    float ts = 0.f, ts2 = 0.f;
    #pragma unroll
    for (int i = 0; i < 6; i++) { ts += sb[i]; ts2 += sb[i + 6]; }
    float mu  = ts  * (1.0f / CDIM);
    float var = ts2 * (1.0f / CDIM) - mu * mu;
    float inv = rsqrtf(var + 1e-5f);
    out[(size_t)t * CDIM + c] = (v - mu) * inv * gw[c] + gb[c];
}

// ---------------- windowed attention (fp32) --------------------------------
__global__ void __launch_bounds__(256)
attn_kernel(const float* __restrict__ qkv, const float* __restrict__ rpb,
            float* __restrict__ out, int shift)
{
    __shared__ float Q[NTOK][33], Kt[NTOK][33], V[NTOK][33];
    __shared__ float S[NTOK][50];
    __shared__ int reg[NTOK];
    int w = blockIdx.x;
    int h = blockIdx.y;
    int tid = threadIdx.x;
    int widx = w & 63;
    int wy = widx >> 3, wx = widx & 7;

    for (int idx = tid; idx < NTOK * HDIM; idx += 256) {
        int n = idx >> 5, d = idx & 31;
        const float* p = qkv + (size_t)(w * NTOK + n) * (3 * CDIM) + h * HDIM + d;
        Q[n][d]  = p[0];
        Kt[n][d] = p[CDIM];
        V[n][d]  = p[2 * CDIM];
    }
    if (shift && tid < NTOK) {
        int ty = tid / 7, tx = tid - ty * 7;
        int sy = wy * 7 + ty, sx = wx * 7 + tx;
        int ry = (sy < 49) ? 0 : ((sy < 53) ? 1 : 2);
        int rx = (sx < 49) ? 0 : ((sx < 53) ? 1 : 2);
        reg[tid] = ry * 3 + rx;
    }
    __syncthreads();

    for (int idx = tid; idx < NTOK * NTOK; idx += 256) {
        int i = idx / NTOK, j = idx - i * NTOK;
        float s = 0.f;
        #pragma unroll
        for (int d = 0; d < HDIM; d++) s += Q[i][d] * Kt[j][d];
        int yi = i / 7, xi = i - yi * 7;
        int yj = j / 7, xj = j - yj * 7;
        int ridx = (yi - yj + 6) * 13 + (xi - xj + 6);
        s = s * QKSCALE + __ldg(&rpb[ridx * NHEADS + h]);
        if (shift && reg[i] != reg[j]) s -= 100.f;
        S[i][j] = s;
    }
    __syncthreads();

    int warp = tid >> 5, lane = tid & 31;
    for (int i = warp; i < NTOK; i += 8) {
        float m = -1e30f;
        for (int j = lane; j < NTOK; j += 32) m = fmaxf(m, S[i][j]);
        #pragma unroll
        for (int o = 16; o; o >>= 1) m = fmaxf(m, __shfl_xor_sync(0xffffffffu, m, o));
        float sum = 0.f;
        for (int j = lane; j < NTOK; j += 32) {
            float e = __expf(S[i][j] - m); S[i][j] = e; sum += e;
        }
        #pragma unroll
        for (int o = 16; o; o >>= 1) sum += __shfl_xor_sync(0xffffffffu, sum, o);
        float inv = 1.f / sum;
        for (int j = lane; j < NTOK; j += 32) S[i][j] *= inv;
    }
    __syncthreads();

    for (int idx = tid; idx < NTOK * HDIM; idx += 256) {
        int i = idx >> 5, d = idx & 31;
        float o = 0.f;
        #pragma unroll
        for (int j = 0; j < NTOK; j++) o += S[i][j] * V[j][d];
        out[(size_t)(w * NTOK + i) * CDIM + h * HDIM + d] = o;
    }
}

// ---------------- tf32 tensor-core GEMM, 3-stage pipeline ------------------
// C[M,N] = A[M,K] @ B[K,N] + bias. CTA tile 128x64, 8 warps, warp tile 32x32.
// mma.sync.m16n8k8.tf32; cp.async 3-stage, ONE __syncthreads per K-iter.
// EPI: 0 = bias, 1 = bias+GELU, 2 = bias+residual, 3 = bias+scatter+residual.

__device__ __forceinline__ float gelu_f(float v) {
    return 0.5f * v * (1.f + erff(v * 0.7071067811865476f));
}

#define ASTRIDE 20
#define BSTRIDE 72
#define STAGES 3

__device__ __forceinline__ void cp16(uint32_t dst, const float* src) {
    asm volatile("cp.async.cg.shared.global [%0], [%1], 16;\n" :: "r"(dst), "l"(src));
}

template<int EPI>
__global__ void __launch_bounds__(256)
tgemm_kernel(const float* __restrict__ A, const float* __restrict__ Bw,
             const float* __restrict__ bias, const float* __restrict__ res,
             float* __restrict__ C, int K, int N, int shift)
{
    __shared__ float As[STAGES][128][ASTRIDE];
    __shared__ float Bs[STAGES][16][BSTRIDE];

    int tid  = threadIdx.x;
    int wid  = tid >> 5;
    int lane = tid & 31;
    int wm = (wid & 3) << 5;     // warp row offset 0..96
    int wn = (wid >> 2) << 5;    // warp col offset 0/32
    int row0 = blockIdx.y << 7;
    int col0 = blockIdx.x << 6;

    // loader indices
    int ar = tid >> 2;           // 0..63 (rows ar, ar+64)
    int aq = (tid & 3) << 2;     // k offset 0,4,8,12
    int bk = tid >> 4;           // 0..15
    int bn = (tid & 15) << 2;    // 0..60

    const float* Ap0 = A + (size_t)(row0 + ar) * K + aq;
    const float* Ap1 = Ap0 + (size_t)64 * K;
    const float* Bp  = Bw + (size_t)bk * N + col0 + bn;

    uint32_t sA0[STAGES], sA1[STAGES], sB[STAGES];
    #pragma unroll
    for (int b = 0; b < STAGES; b++) {
        sA0[b] = (uint32_t)__cvta_generic_to_shared(&As[b][ar][aq]);
        sA1[b] = (uint32_t)__cvta_generic_to_shared(&As[b][ar + 64][aq]);
        sB[b]  = (uint32_t)__cvta_generic_to_shared(&Bs[b][bk][bn]);
    }

    float acc[2][4][4];
    #pragma unroll
    for (int mt = 0; mt < 2; mt++)
        #pragma unroll
        for (int nt = 0; nt < 4; nt++)
            #pragma unroll
            for (int i = 0; i < 4; i++) acc[mt][nt][i] = 0.f;

    // ldmatrix addressing (A fragments)
    int lrow = lane & 7;
    int seg  = lane >> 3;             // 0..3
    int arow = wm + ((seg & 1) << 3) + lrow;   // + mt*16
    int acol = (seg >> 1) << 2;                // + kk

    int nIter = K >> 4;

    // prologue: stages 0 and 1
    #pragma unroll
    for (int s = 0; s < 2; s++) {
        int k0 = s << 4;
        cp16(sA0[s], Ap0 + k0);
        cp16(sA1[s], Ap1 + k0);
        cp16(sB[s],  Bp + (size_t)k0 * N);
        asm volatile("cp.async.commit_group;\n");
    }

    for (int it = 0; it < nIter; it++) {
        int buf = it % STAGES;
        if (it + 1 < nIter) asm volatile("cp.async.wait_group 1;\n");
        else                asm volatile("cp.async.wait_group 0;\n");
        __syncthreads();
        // prefetch stage it+2 into buffer (it+2)%3 (safe: that buffer was
        // last read in iter it-1, and the barrier above proves all warps
        // have finished it).
        if (it + 2 < nIter) {
            int nb = (it + 2) % STAGES;
            int k0 = (it + 2) << 4;
            cp16(sA0[nb], Ap0 + k0);
            cp16(sA1[nb], Ap1 + k0);
            cp16(sB[nb],  Bp + (size_t)k0 * N);
            asm volatile("cp.async.commit_group;\n");
        }
        #pragma unroll
        for (int kk = 0; kk < 16; kk += 8) {
            uint32_t afr[2][4];
            #pragma unroll
            for (int mt = 0; mt < 2; mt++) {
                uint32_t addr = (uint32_t)__cvta_generic_to_shared(
                    &As[buf][arow + (mt << 4)][kk + acol]);
                asm volatile(
                    "ldmatrix.sync.aligned.m8n8.x4.shared.b16 {%0,%1,%2,%3}, [%4];\n"
                    : "=r"(afr[mt][0]), "=r"(afr[mt][1]),
                      "=r"(afr[mt][2]), "=r"(afr[mt][3])
                    : "r"(addr));
            }
            uint32_t bfr[4][2];
            int bkr = kk + (lane & 3);
            int bnc = wn + (lane >> 2);
            #pragma unroll
            for (int nt = 0; nt < 4; nt++) {
                bfr[nt][0] = __float_as_uint(Bs[buf][bkr][bnc + (nt << 3)]);
                bfr[nt][1] = __float_as_uint(Bs[buf][bkr + 4][bnc + (nt << 3)]);
            }
            #pragma unroll
            for (int mt = 0; mt < 2; mt++)
                #pragma unroll
                for (int nt = 0; nt < 4; nt++) {
                    asm volatile(
                        "mma.sync.aligned.m16n8k8.row.col.f32.tf32.tf32.f32 "
                        "{%0,%1,%2,%3},{%4,%5,%6,%7},{%8,%9},{%0,%1,%2,%3};\n"
                        : "+f"(acc[mt][nt][0]), "+f"(acc[mt][nt][1]),
                          "+f"(acc[mt][nt][2]), "+f"(acc[mt][nt][3])
                        : "r"(afr[mt][0]), "r"(afr[mt][1]),
                          "r"(afr[mt][2]), "r"(afr[mt][3]),
                          "r"(bfr[nt][0]), "r"(bfr[nt][1]));
                }
        }
    }

    // epilogue: c0:(r,c) c1:(r,c+1) c2:(r+8,c) c3:(r+8,c+1); r=lane/4, c=2*(lane%4)
    int erow = (lane >> 2);
    int ecol = (lane & 3) << 1;
    #pragma unroll
    for (int mt = 0; mt < 2; mt++) {
        #pragma unroll
        for (int half = 0; half < 2; half++) {
            int m = row0 + wm + (mt << 4) + erow + (half << 3);
            size_t roff;
            if (EPI == 3) roff = (size_t)map_row(m, shift) * N;
            else          roff = (size_t)m * N;
            #pragma unroll
            for (int nt = 0; nt < 4; nt++) {
                int col = col0 + wn + (nt << 3) + ecol;
                float v0 = acc[mt][nt][half * 2 + 0] + bias[col];
                float v1 = acc[mt][nt][half * 2 + 1] + bias[col + 1];
                if (EPI == 1) { v0 = gelu_f(v0); v1 = gelu_f(v1); }
                if (EPI == 2 || EPI == 3) {
                    float2 r = *(const float2*)&res[roff + col];
                    v0 += r.x; v1 += r.y;
                }
                float2 o; o.x = v0; o.y = v1;
                *(float2*)&C[roff + col] = o;
            }
        }
    }
}

// ---------------- launcher -------------------------------------------------
extern "C" void kernel_launch(void* const* d_in, const int* in_sizes, int n_in,
                              void* d_out, int out_size)
{
    const float* x     = (const float*)d_in[0];
    const float* ln1g  = (const float*)d_in[1];
    const float* ln1b  = (const float*)d_in[2];
    const float* qkvw  = (const float*)d_in[3];
    const float* qkvb  = (const float*)d_in[4];
    const float* rpb   = (const float*)d_in[5];
    const float* projw = (const float*)d_in[6];
    const float* projb = (const float*)d_in[7];
    const float* ln2g  = (const float*)d_in[8];
    const float* ln2b  = (const float*)d_in[9];
    const float* fc1w  = (const float*)d_in[10];
    const float* fc1b  = (const float*)d_in[11];
    const float* fc2w  = (const float*)d_in[12];
    const float* fc2b  = (const float*)d_in[13];

    float *p_win, *p_qkv, *p_att, *p_x1, *p_y, *p_h1, *p_x0;
    cudaGetSymbolAddress((void**)&p_win, g_win);
    cudaGetSymbolAddress((void**)&p_qkv, g_qkv);
    cudaGetSymbolAddress((void**)&p_att, g_att);
    cudaGetSymbolAddress((void**)&p_x1,  g_x1);
    cudaGetSymbolAddress((void**)&p_y,   g_y);
    cudaGetSymbolAddress((void**)&p_h1,  g_h1);
    cudaGetSymbolAddress((void**)&p_x0,  g_x0);

    const int MB = MROWS / 128;   // 1568

    for (int dep = 0; dep < 2; dep++) {
        int shift = dep ? 3 : 0;
        const float* src = dep ? (const float*)p_x0 : x;
        float* dst = dep ? (float*)d_out : p_x0;

        ln_part_kernel<<<MROWS, 192>>>(src, ln1g + dep * CDIM, ln1b + dep * CDIM,
                                       p_win, shift);
        tgemm_kernel<0><<<dim3(9, MB), 256>>>(p_win, qkvw + (size_t)dep * CDIM * 3 * CDIM,
                                              qkvb + dep * 3 * CDIM, nullptr,
                                              p_qkv, CDIM, 3 * CDIM, 0);
        attn_kernel<<<dim3(NWIN, NHEADS), 256>>>(p_qkv, rpb + dep * 169 * NHEADS,
                                                 p_att, shift);
        tgemm_kernel<3><<<dim3(3, MB), 256>>>(p_att, projw + (size_t)dep * CDIM * CDIM,
                                              projb + dep * CDIM, src,
                                              p_x1, CDIM, CDIM, shift);
        ln_kernel<<<MROWS, 192>>>(p_x1, ln2g + dep * CDIM, ln2b + dep * CDIM, p_y);
        tgemm_kernel<1><<<dim3(12, MB), 256>>>(p_y, fc1w + (size_t)dep * CDIM * HID,
                                               fc1b + dep * HID, nullptr,
                                               p_h1, CDIM, HID, 0);
        tgemm_kernel<2><<<dim3(3, MB), 256>>>(p_h1, fc2w + (size_t)dep * HID * CDIM,
                                              fc2b + dep * CDIM, p_x1,
                                              dst, HID, CDIM, 0);
    }
}

// round 11
// speedup vs baseline: 1.0362x; 1.0362x over previous
#include <cuda_runtime.h>
#include <cstdint>

#define CDIM 192
#define NHEADS 6
#define HDIM 32
#define NTOK 49
#define NWIN 4096
#define MROWS 200704
#define HID 768
#define QKSCALE 0.17677669529663687f

// ---------------- scratch buffers (static device memory; no allocs) --------
__device__ __align__(128) float g_win[(size_t)MROWS * CDIM];
__device__ __align__(128) float g_qkv[(size_t)MROWS * (3 * CDIM)];
__device__ __align__(128) float g_att[(size_t)MROWS * CDIM];
__device__ __align__(128) float g_x1[(size_t)MROWS * CDIM];
__device__ __align__(128) float g_y[(size_t)MROWS * CDIM];
__device__ __align__(128) float g_h1[(size_t)MROWS * HID];
__device__ __align__(128) float g_x0[(size_t)MROWS * CDIM];

__device__ __forceinline__ int map_row(int m, int shift) {
    int w = m / NTOK;
    int n = m - w * NTOK;
    int b = w >> 6;
    int widx = w & 63;
    int wy = widx >> 3, wx = widx & 7;
    int ty = n / 7, tx = n - ty * 7;
    int sy = wy * 7 + ty + shift; if (sy >= 56) sy -= 56;
    int sx = wx * 7 + tx + shift; if (sx >= 56) sx -= 56;
    return b * 3136 + sy * 56 + sx;
}

// ---------------- LayerNorm kernels ----------------------------------------
__global__ void ln_part_kernel(const float* __restrict__ x,
                               const float* __restrict__ gw,
                               const float* __restrict__ gb,
                               float* __restrict__ out, int shift)
{
    int t = blockIdx.x;
    int src = map_row(t, shift);
    int c = threadIdx.x;
    float v = x[(size_t)src * CDIM + c];
    __shared__ float sb[12];
    float s = v, s2 = v * v;
    #pragma unroll
    for (int o = 16; o; o >>= 1) {
        s  += __shfl_xor_sync(0xffffffffu, s, o);
        s2 += __shfl_xor_sync(0xffffffffu, s2, o);
    }
    int warp = c >> 5;
    if ((c & 31) == 0) { sb[warp] = s; sb[warp + 6] = s2; }
    __syncthreads();
    float ts = 0.f, ts2 = 0.f;
    #pragma unroll
    for (int i = 0; i < 6; i++) { ts += sb[i]; ts2 += sb[i + 6]; }
    float mu  = ts  * (1.0f / CDIM);
    float var = ts2 * (1.0f / CDIM) - mu * mu;
    float inv = rsqrtf(var + 1e-5f);
    out[(size_t)t * CDIM + c] = (v - mu) * inv * gw[c] + gb[c];
}

__global__ void ln_kernel(const float* __restrict__ x,
                          const float* __restrict__ gw,
                          const float* __restrict__ gb,
                          float* __restrict__ out)
{
    int t = blockIdx.x;
    int c = threadIdx.x;
    float v = x[(size_t)t * CDIM + c];
    __shared__ float sb[12];
    float s = v, s2 = v * v;
    #pragma unroll
    for (int o = 16; o; o >>= 1) {
        s  += __shfl_xor_sync(0xffffffffu, s, o);
        s2 += __shfl_xor_sync(0xffffffffu, s2, o);
    }
    int warp = c >> 5;
    if ((c & 31) == 0) { sb[warp] = s; sb[warp + 6] = s2; }
    __syncthreads();
    float ts = 0.f, ts2 = 0.f;
    #pragma unroll
    for (int i = 0; i < 6; i++) { ts += sb[i]; ts2 += sb[i + 6]; }
    float mu  = ts  * (1.0f / CDIM);
    float var = ts2 * (1.0f / CDIM) - mu * mu;
    float inv = rsqrtf(var + 1e-5f);
    out[(size_t)t * CDIM + c] = (v - mu) * inv * gw[c] + gb[c];
}

// ---------------- windowed attention (fp32) --------------------------------
__global__ void __launch_bounds__(256)
attn_kernel(const float* __restrict__ qkv, const float* __restrict__ rpb,
            float* __restrict__ out, int shift)
{
    __shared__ float Q[NTOK][33], Kt[NTOK][33], V[NTOK][33];
    __shared__ float S[NTOK][50];
    __shared__ int reg[NTOK];
    int w = blockIdx.x;
    int h = blockIdx.y;
    int tid = threadIdx.x;
    int widx = w & 63;
    int wy = widx >> 3, wx = widx & 7;

    for (int idx = tid; idx < NTOK * HDIM; idx += 256) {
        int n = idx >> 5, d = idx & 31;
        const float* p = qkv + (size_t)(w * NTOK + n) * (3 * CDIM) + h * HDIM + d;
        Q[n][d]  = p[0];
        Kt[n][d] = p[CDIM];
        V[n][d]  = p[2 * CDIM];
    }
    if (shift && tid < NTOK) {
        int ty = tid / 7, tx = tid - ty * 7;
        int sy = wy * 7 + ty, sx = wx * 7 + tx;
        int ry = (sy < 49) ? 0 : ((sy < 53) ? 1 : 2);
        int rx = (sx < 49) ? 0 : ((sx < 53) ? 1 : 2);
        reg[tid] = ry * 3 + rx;
    }
    __syncthreads();

    for (int idx = tid; idx < NTOK * NTOK; idx += 256) {
        int i = idx / NTOK, j = idx - i * NTOK;
        float s = 0.f;
        #pragma unroll
        for (int d = 0; d < HDIM; d++) s += Q[i][d] * Kt[j][d];
        int yi = i / 7, xi = i - yi * 7;
        int yj = j / 7, xj = j - yj * 7;
        int ridx = (yi - yj + 6) * 13 + (xi - xj + 6);
        s = s * QKSCALE + __ldg(&rpb[ridx * NHEADS + h]);
        if (shift && reg[i] != reg[j]) s -= 100.f;
        S[i][j] = s;
    }
    __syncthreads();

    int warp = tid >> 5, lane = tid & 31;
    for (int i = warp; i < NTOK; i += 8) {
        float m = -1e30f;
        for (int j = lane; j < NTOK; j += 32) m = fmaxf(m, S[i][j]);
        #pragma unroll
        for (int o = 16; o; o >>= 1) m = fmaxf(m, __shfl_xor_sync(0xffffffffu, m, o));
        float sum = 0.f;
        for (int j = lane; j < NTOK; j += 32) {
            float e = __expf(S[i][j] - m); S[i][j] = e; sum += e;
        }
        #pragma unroll
        for (int o = 16; o; o >>= 1) sum += __shfl_xor_sync(0xffffffffu, sum, o);
        float inv = 1.f / sum;
        for (int j = lane; j < NTOK; j += 32) S[i][j] *= inv;
    }
    __syncthreads();

    for (int idx = tid; idx < NTOK * HDIM; idx += 256) {
        int i = idx >> 5, d = idx & 31;
        float o = 0.f;
        #pragma unroll
        for (int j = 0; j < NTOK; j++) o += S[i][j] * V[j][d];
        out[(size_t)(w * NTOK + i) * CDIM + h * HDIM + d] = o;
    }
}

// ---------------- tf32 tensor-core GEMM, 4 warps, warp tile 64x32 ----------
// C[M,N] = A[M,K] @ B[K,N] + bias. CTA tile 128x64, 128 threads, 4 warps
// (2x2 warp grid, warp tile 64x32 = 16 independent MMAs per k8 step).
// mma.sync.m16n8k8.tf32; cp.async 3-stage, one __syncthreads per K-iter.
// EPI: 0 = bias, 1 = bias+GELU, 2 = bias+residual, 3 = bias+scatter+residual.

__device__ __forceinline__ float gelu_f(float v) {
    return 0.5f * v * (1.f + erff(v * 0.7071067811865476f));
}

#define ASTRIDE 20
#define BSTRIDE 72
#define STAGES 3

__device__ __forceinline__ void cp16(uint32_t dst, const float* src) {
    asm volatile("cp.async.cg.shared.global [%0], [%1], 16;\n" :: "r"(dst), "l"(src));
}

template<int EPI>
__global__ void __launch_bounds__(128, 4)
tgemm_kernel(const float* __restrict__ A, const float* __restrict__ Bw,
             const float* __restrict__ bias, const float* __restrict__ res,
             float* __restrict__ C, int K, int N, int shift)
{
    __shared__ float As[STAGES][128][ASTRIDE];
    __shared__ float Bs[STAGES][16][BSTRIDE];

    int tid  = threadIdx.x;
    int wid  = tid >> 5;
    int lane = tid & 31;
    int wm = (wid & 1) << 6;     // warp row offset 0/64
    int wn = (wid >> 1) << 5;    // warp col offset 0/32
    int row0 = blockIdx.y << 7;
    int col0 = blockIdx.x << 6;

    // loader indices (128 threads)
    int ar = tid >> 2;           // 0..31 (rows ar, +32, +64, +96)
    int aq = (tid & 3) << 2;     // k offset 0,4,8,12
    int bk = tid >> 4;           // 0..7  (rows bk, bk+8)
    int bn = (tid & 15) << 2;    // 0..60

    const float* Ap = A + (size_t)(row0 + ar) * K + aq;
    const float* Bp = Bw + (size_t)bk * N + col0 + bn;

    uint32_t sA[STAGES], sB[STAGES];
    #pragma unroll
    for (int b = 0; b < STAGES; b++) {
        sA[b] = (uint32_t)__cvta_generic_to_shared(&As[b][ar][aq]);
        sB[b] = (uint32_t)__cvta_generic_to_shared(&Bs[b][bk][bn]);
    }
    const uint32_t aRowStep = 32u * ASTRIDE * 4u;     // 32 rows
    const uint32_t bRowStep = 8u * BSTRIDE * 4u;      // 8 rows

    float acc[4][4][4];
    #pragma unroll
    for (int mt = 0; mt < 4; mt++)
        #pragma unroll
        for (int nt = 0; nt < 4; nt++)
            #pragma unroll
            for (int i = 0; i < 4; i++) acc[mt][nt][i] = 0.f;

    // ldmatrix addressing (A fragments)
    int lrow = lane & 7;
    int seg  = lane >> 3;             // 0..3
    int arow = wm + ((seg & 1) << 3) + lrow;   // + mt*16
    int acol = (seg >> 1) << 2;                // + kk

    int nIter = K >> 4;

    #define STAGE_LD(s_, k0_) do {                                            \
        cp16(sA[s_],                 Ap + (k0_));                              \
        cp16(sA[s_] + aRowStep,      Ap + (size_t)32 * K + (k0_));             \
        cp16(sA[s_] + 2 * aRowStep,  Ap + (size_t)64 * K + (k0_));             \
        cp16(sA[s_] + 3 * aRowStep,  Ap + (size_t)96 * K + (k0_));             \
        cp16(sB[s_],                 Bp + (size_t)(k0_) * N);                  \
        cp16(sB[s_] + bRowStep,      Bp + (size_t)((k0_) + 8) * N);            \
        asm volatile("cp.async.commit_group;\n");                              \
    } while (0)

    // prologue: stages 0 and 1
    STAGE_LD(0, 0);
    STAGE_LD(1, 16);

    for (int it = 0; it < nIter; it++) {
        int buf = it % STAGES;
        if (it + 1 < nIter) asm volatile("cp.async.wait_group 1;\n");
        else                asm volatile("cp.async.wait_group 0;\n");
        __syncthreads();
        if (it + 2 < nIter) {
            int nb = (it + 2) % STAGES;
            int k0 = (it + 2) << 4;
            STAGE_LD(nb, k0);
        }
        #pragma unroll
        for (int kk = 0; kk < 16; kk += 8) {
            uint32_t afr[4][4];
            #pragma unroll
            for (int mt = 0; mt < 4; mt++) {
                uint32_t addr = (uint32_t)__cvta_generic_to_shared(
                    &As[buf][arow + (mt << 4)][kk + acol]);
                asm volatile(
                    "ldmatrix.sync.aligned.m8n8.x4.shared.b16 {%0,%1,%2,%3}, [%4];\n"
                    : "=r"(afr[mt][0]), "=r"(afr[mt][1]),
                      "=r"(afr[mt][2]), "=r"(afr[mt][3])
                    : "r"(addr));
            }
            uint32_t bfr[4][2];
            int bkr = kk + (lane & 3);
            int bnc = wn + (lane >> 2);
            #pragma unroll
            for (int nt = 0; nt < 4; nt++) {
                bfr[nt][0] = __float_as_uint(Bs[buf][bkr][bnc + (nt << 3)]);
                bfr[nt][1] = __float_as_uint(Bs[buf][bkr + 4][bnc + (nt << 3)]);
            }
            #pragma unroll
            for (int mt = 0; mt < 4; mt++)
                #pragma unroll
                for (int nt = 0; nt < 4; nt++) {
                    asm volatile(
                        "mma.sync.aligned.m16n8k8.row.col.f32.tf32.tf32.f32 "
                        "{%0,%1,%2,%3},{%4,%5,%6,%7},{%8,%9},{%0,%1,%2,%3};\n"
                        : "+f"(acc[mt][nt][0]), "+f"(acc[mt][nt][1]),
                          "+f"(acc[mt][nt][2]), "+f"(acc[mt][nt][3])
                        : "r"(afr[mt][0]), "r"(afr[mt][1]),
                          "r"(afr[mt][2]), "r"(afr[mt][3]),
                          "r"(bfr[nt][0]), "r"(bfr[nt][1]));
                }
        }
    }

    // epilogue: c0:(r,c) c1:(r,c+1) c2:(r+8,c) c3:(r+8,c+1); r=lane/4, c=2*(lane%4)
    int erow = (lane >> 2);
    int ecol = (lane & 3) << 1;
    #pragma unroll
    for (int mt = 0; mt < 4; mt++) {
        #pragma unroll
        for (int half = 0; half < 2; half++) {
            int m = row0 + wm + (mt << 4) + erow + (half << 3);
            size_t roff;
            if (EPI == 3) roff = (size_t)map_row(m, shift) * N;
            else          roff = (size_t)m * N;
            #pragma unroll
            for (int nt = 0; nt < 4; nt++) {
                int col = col0 + wn + (nt << 3) + ecol;
                float v0 = acc[mt][nt][half * 2 + 0] + bias[col];
                float v1 = acc[mt][nt][half * 2 + 1] + bias[col + 1];
                if (EPI == 1) { v0 = gelu_f(v0); v1 = gelu_f(v1); }
                if (EPI == 2 || EPI == 3) {
                    float2 r = *(const float2*)&res[roff + col];
                    v0 += r.x; v1 += r.y;
                }
                float2 o; o.x = v0; o.y = v1;
                *(float2*)&C[roff + col] = o;
            }
        }
    }
}

// ---------------- launcher -------------------------------------------------
extern "C" void kernel_launch(void* const* d_in, const int* in_sizes, int n_in,
                              void* d_out, int out_size)
{
    const float* x     = (const float*)d_in[0];
    const float* ln1g  = (const float*)d_in[1];
    const float* ln1b  = (const float*)d_in[2];
    const float* qkvw  = (const float*)d_in[3];
    const float* qkvb  = (const float*)d_in[4];
    const float* rpb   = (const float*)d_in[5];
    const float* projw = (const float*)d_in[6];
    const float* projb = (const float*)d_in[7];
    const float* ln2g  = (const float*)d_in[8];
    const float* ln2b  = (const float*)d_in[9];
    const float* fc1w  = (const float*)d_in[10];
    const float* fc1b  = (const float*)d_in[11];
    const float* fc2w  = (const float*)d_in[12];
    const float* fc2b  = (const float*)d_in[13];

    float *p_win, *p_qkv, *p_att, *p_x1, *p_y, *p_h1, *p_x0;
    cudaGetSymbolAddress((void**)&p_win, g_win);
    cudaGetSymbolAddress((void**)&p_qkv, g_qkv);
    cudaGetSymbolAddress((void**)&p_att, g_att);
    cudaGetSymbolAddress((void**)&p_x1,  g_x1);
    cudaGetSymbolAddress((void**)&p_y,   g_y);
    cudaGetSymbolAddress((void**)&p_h1,  g_h1);
    cudaGetSymbolAddress((void**)&p_x0,  g_x0);

    const int MB = MROWS / 128;   // 1568

    for (int dep = 0; dep < 2; dep++) {
        int shift = dep ? 3 : 0;
        const float* src = dep ? (const float*)p_x0 : x;
        float* dst = dep ? (float*)d_out : p_x0;

        ln_part_kernel<<<MROWS, 192>>>(src, ln1g + dep * CDIM, ln1b + dep * CDIM,
                                       p_win, shift);
        tgemm_kernel<0><<<dim3(9, MB), 128>>>(p_win, qkvw + (size_t)dep * CDIM * 3 * CDIM,
                                              qkvb + dep * 3 * CDIM, nullptr,
                                              p_qkv, CDIM, 3 * CDIM, 0);
        attn_kernel<<<dim3(NWIN, NHEADS), 256>>>(p_qkv, rpb + dep * 169 * NHEADS,
                                                 p_att, shift);
        tgemm_kernel<3><<<dim3(3, MB), 128>>>(p_att, projw + (size_t)dep * CDIM * CDIM,
                                              projb + dep * CDIM, src,
                                              p_x1, CDIM, CDIM, shift);
        ln_kernel<<<MROWS, 192>>>(p_x1, ln2g + dep * CDIM, ln2b + dep * CDIM, p_y);
        tgemm_kernel<1><<<dim3(12, MB), 128>>>(p_y, fc1w + (size_t)dep * CDIM * HID,
                                               fc1b + dep * HID, nullptr,
                                               p_h1, CDIM, HID, 0);
        tgemm_kernel<2><<<dim3(3, MB), 128>>>(p_h1, fc2w + (size_t)dep * HID * CDIM,
                                              fc2b + dep * CDIM, p_x1,
                                              dst, HID, CDIM, 0);
    }
}